// round 1
// baseline (speedup 1.0000x reference)
#include <cuda_runtime.h>

// Problem constants
#define NB 8      // batch
#define NC 12     // channels
#define GD 8      // grid depth (z)
#define GH 16     // grid height
#define GW 16     // grid width
#define IH 1024   // image height
#define IW 1024   // image width

// Transposed grid: [n][y][x][z][c], c contiguous (12 floats = 3 float4 per (z))
__device__ float g_t[NB * GH * GW * GD * NC];

// src layout: [n][c][z][y][x]
__global__ __launch_bounds__(256) void transpose_grid_kernel(const float* __restrict__ src) {
    int idx = blockIdx.x * 256 + threadIdx.x;
    if (idx >= NB * NC * GD * GH * GW) return;
    int x = idx & 15;
    int y = (idx >> 4) & 15;
    int z = (idx >> 8) & 7;
    int c = (idx >> 11) % NC;
    int n = idx / (NC * GD * GH * GW);
    g_t[((((n * GH + y) * GW + x) * GD + z) * NC) + c] = src[idx];
}

__global__ __launch_bounds__(256) void slice_kernel(
    const float* __restrict__ guide,   // [n][1][i][j] = 8M floats
    float* __restrict__ out)           // [n][c][i][j]
{
    int pix = blockIdx.x * 256 + threadIdx.x;   // 8*1024*1024 pixels
    int n = pix >> 20;
    int ij = pix & 0xFFFFF;
    int i = ij >> 10;
    int j = ij & 1023;

    float g = guide[pix];

    float gx = ((float)j + 0.5f) * (16.0f / 1024.0f);
    float gy = ((float)i + 0.5f) * (16.0f / 1024.0f);
    float gz = g * 8.0f;

    float fx = floorf(gx - 0.5f);
    float fy = floorf(gy - 0.5f);
    float fz = floorf(gz - 0.5f);
    float wx1 = gx - 0.5f - fx;
    float wy1 = gy - 0.5f - fy;
    float wz1 = gz - 0.5f - fz;

    int ix = (int)fx, iy = (int)fy, iz = (int)fz;
    int x0 = max(0, min(GW - 1, ix));
    int x1 = max(0, min(GW - 1, ix + 1));
    int y0 = max(0, min(GH - 1, iy));
    int y1 = max(0, min(GH - 1, iy + 1));
    int z0 = max(0, min(GD - 1, iz));
    int z1 = max(0, min(GD - 1, iz + 1));

    const float4* base = (const float4*)(g_t) + (size_t)n * (GH * GW * GD * 3);

    float acc[12];
#pragma unroll
    for (int c = 0; c < 12; c++) acc[c] = 0.0f;

    float wyv[2] = {1.0f - wy1, wy1};
    float wxv[2] = {1.0f - wx1, wx1};
    int ys[2] = {y0, y1};
    int xs[2] = {x0, x1};

#pragma unroll
    for (int a = 0; a < 2; a++) {
#pragma unroll
        for (int b = 0; b < 2; b++) {
            float wxy = wyv[a] * wxv[b];
            float wa = wxy * (1.0f - wz1);
            float wb = wxy * wz1;
            int corner = (ys[a] * GW + xs[b]) * GD;  // in z-units
            const float4* p0 = base + (corner + z0) * 3;
            const float4* p1 = base + (corner + z1) * 3;
#pragma unroll
            for (int q = 0; q < 3; q++) {
                float4 v0 = p0[q];
                float4 v1 = p1[q];
                acc[q * 4 + 0] += wa * v0.x + wb * v1.x;
                acc[q * 4 + 1] += wa * v0.y + wb * v1.y;
                acc[q * 4 + 2] += wa * v0.z + wb * v1.z;
                acc[q * 4 + 3] += wa * v0.w + wb * v1.w;
            }
        }
    }

    size_t obase = ((size_t)(n * NC)) << 20;
    int off = (i << 10) | j;
#pragma unroll
    for (int c = 0; c < 12; c++)
        out[obase + (((size_t)c) << 20) + off] = acc[c];
}

extern "C" void kernel_launch(void* const* d_in, const int* in_sizes, int n_in,
                              void* d_out, int out_size) {
    // Robustly identify inputs by element count.
    const float* grid_src = nullptr;
    const float* guide = nullptr;
    for (int k = 0; k < n_in; k++) {
        if (in_sizes[k] == NB * NC * GD * GH * GW) grid_src = (const float*)d_in[k];
        else if (in_sizes[k] == NB * IH * IW) guide = (const float*)d_in[k];
    }
    float* out = (float*)d_out;

    int ne = NB * NC * GD * GH * GW;
    transpose_grid_kernel<<<(ne + 255) / 256, 256>>>(grid_src);

    int pixels = NB * IH * IW;
    slice_kernel<<<pixels / 256, 256>>>(guide, out);
}

// round 2
// speedup vs baseline: 1.9138x; 1.9138x over previous
#include <cuda_runtime.h>

#define NB 8
#define NC 12
#define GD 8
#define GH 16
#define GW 16
#define IH 1024
#define IW 1024

// Transposed grid: [n][y][x][z][c], c contiguous. 96 floats per (y,x,z... ) per x-cell: 8z*12c
__device__ float g_t[NB * GH * GW * GD * NC];

// src layout: [n][c][z][y][x]
__global__ __launch_bounds__(256) void transpose_grid_kernel(const float* __restrict__ src) {
    int idx = blockIdx.x * 256 + threadIdx.x;
    if (idx >= NB * NC * GD * GH * GW) return;
    int x = idx & 15;
    int y = (idx >> 4) & 15;
    int z = (idx >> 8) & 7;
    int c = (idx >> 11) % NC;
    int n = idx / (NC * GD * GH * GW);
    g_t[((((n * GH + y) * GW + x) * GD + z) * NC) + c] = src[idx];
}

// One block per (n, i) output row. Shared: y-interpolated grid line,
// padded to 25 float4 (=100 floats) per x to avoid bank conflicts.
#define XPAD 25   // float4 units per x (24 used + 1 pad)

__global__ __launch_bounds__(256) void slice_kernel(
    const float* __restrict__ guide,   // [n][i][j]
    float* __restrict__ out)           // [n][c][i][j]
{
    __shared__ float4 sm[GW * XPAD];   // 16*25*16B = 6.4 KB

    int bid = blockIdx.x;              // n*1024 + i
    int n = bid >> 10;
    int i = bid & 1023;
    int tid = threadIdx.x;

    // ---- y-interp precompute ----
    float gy = ((float)i + 0.5f) * (16.0f / 1024.0f);
    float fy = floorf(gy - 0.5f);
    float wy1 = gy - 0.5f - fy;
    int iy = (int)fy;
    int y0 = max(0, min(GH - 1, iy));
    int y1 = max(0, min(GH - 1, iy + 1));

    const float4* r0 = (const float4*)(g_t + ((size_t)(n * GH + y0) * GW) * (GD * NC));
    const float4* r1 = (const float4*)(g_t + ((size_t)(n * GH + y1) * GW) * (GD * NC));

    // 16 x * 24 float4 = 384 float4 to produce
#pragma unroll
    for (int v = tid; v < GW * 24; v += 256) {
        int x = v / 24;
        int zc = v - x * 24;
        float4 a = r0[v];
        float4 b = r1[v];
        float4 o;
        o.x = fmaf(wy1, b.x - a.x, a.x);
        o.y = fmaf(wy1, b.y - a.y, a.y);
        o.z = fmaf(wy1, b.z - a.z, a.z);
        o.w = fmaf(wy1, b.w - a.w, a.w);
        sm[x * XPAD + zc] = o;
    }
    __syncthreads();

    // ---- 4 pixels per thread, strided by 256 ----
    const float* grow = guide + (((size_t)n << 10) + i) * 1024;
    size_t obase = (((size_t)(n * NC)) << 20) + ((size_t)i << 10);

#pragma unroll
    for (int p = 0; p < 4; p++) {
        int j = tid + (p << 8);
        float g = grow[j];

        float gx = ((float)j + 0.5f) * (16.0f / 1024.0f);
        float fx = floorf(gx - 0.5f);
        float wx1 = gx - 0.5f - fx;
        int ix = (int)fx;
        int x0 = max(0, min(GW - 1, ix));
        int x1 = max(0, min(GW - 1, ix + 1));

        float gz = g * 8.0f;
        float fz = floorf(gz - 0.5f);
        float wz1 = gz - 0.5f - fz;
        int iz = (int)fz;
        int z0 = max(0, min(GD - 1, iz));
        int z1 = max(0, min(GD - 1, iz + 1));

        float wx0 = 1.0f - wx1;
        float wz0 = 1.0f - wz1;
        float w00 = wx0 * wz0;   // x0,z0
        float w01 = wx0 * wz1;   // x0,z1
        float w10 = wx1 * wz0;   // x1,z0
        float w11 = wx1 * wz1;   // x1,z1

        const float4* A = sm + x0 * XPAD;
        const float4* B = sm + x1 * XPAD;
        int a0 = z0 * 3, a1 = z1 * 3;

#pragma unroll
        for (int q = 0; q < 3; q++) {
            float4 v00 = A[a0 + q];
            float4 v01 = A[a1 + q];
            float4 v10 = B[a0 + q];
            float4 v11 = B[a1 + q];
            float o0 = w00 * v00.x + w01 * v01.x + w10 * v10.x + w11 * v11.x;
            float o1 = w00 * v00.y + w01 * v01.y + w10 * v10.y + w11 * v11.y;
            float o2 = w00 * v00.z + w01 * v01.z + w10 * v10.z + w11 * v11.z;
            float o3 = w00 * v00.w + w01 * v01.w + w10 * v10.w + w11 * v11.w;
            int c = q * 4;
            out[obase + (((size_t)(c + 0)) << 20) + j] = o0;
            out[obase + (((size_t)(c + 1)) << 20) + j] = o1;
            out[obase + (((size_t)(c + 2)) << 20) + j] = o2;
            out[obase + (((size_t)(c + 3)) << 20) + j] = o3;
        }
    }
}

extern "C" void kernel_launch(void* const* d_in, const int* in_sizes, int n_in,
                              void* d_out, int out_size) {
    const float* grid_src = nullptr;
    const float* guide = nullptr;
    for (int k = 0; k < n_in; k++) {
        if (in_sizes[k] == NB * NC * GD * GH * GW) grid_src = (const float*)d_in[k];
        else if (in_sizes[k] == NB * IH * IW) guide = (const float*)d_in[k];
    }
    float* out = (float*)d_out;

    int ne = NB * NC * GD * GH * GW;
    transpose_grid_kernel<<<(ne + 255) / 256, 256>>>(grid_src);

    slice_kernel<<<NB * IH, 256>>>(guide, out);
}